// round 13
// baseline (speedup 1.0000x reference)
#include <cuda_runtime.h>
#include <cuda_bf16.h>
#include <stdint.h>

#define NNODES  50000
#define HID     128
#define NEDGES  600000
#define OUTC    40
#define NLAYERS 3
#define NTILES  391            // ceil(50000/128)
#define SCB     49             // ceil(50000/1024) scan blocks

// ---------------- persistent scratch (__device__ globals, zero-init) -------
__device__ float g_h[(size_t)NNODES * HID];
__device__ __nv_bfloat16 g_zhi[(size_t)NTILES * 128 * HID];   // row-major split z
__device__ __nv_bfloat16 g_zlo[(size_t)NTILES * 128 * HID];
// per layer: [W1hi, W1lo, W2hi, W2lo], each W^T [n][k] row-major 128x128 bf16
__device__ __nv_bfloat16 g_wsp[(size_t)NLAYERS * 4 * HID * HID];
// Wc^T padded to [64][128], hi then lo (pad rows never written -> stay zero)
__device__ __nv_bfloat16 g_wc[2 * 64 * HID];
__device__ int g_deg[NNODES];
__device__ int g_rowptr[NNODES + 1];
__device__ int g_cur[NNODES];
__device__ int g_col[NEDGES];

// ---------------- mma.sync / ldmatrix (sm_80+ baseline, non-'a') -----------
__device__ __forceinline__ uint32_t smem_u32(const void* p) {
    uint32_t a;
    asm("{ .reg .u64 t; cvta.to.shared.u64 t, %1; cvt.u32.u64 %0, t; }"
        : "=r"(a) : "l"(p));
    return a;
}
__device__ __forceinline__ void ldsm_x4(uint32_t* r, uint32_t addr) {
    asm volatile("ldmatrix.sync.aligned.m8n8.x4.shared.b16 {%0,%1,%2,%3}, [%4];"
                 : "=r"(r[0]), "=r"(r[1]), "=r"(r[2]), "=r"(r[3]) : "r"(addr));
}
__device__ __forceinline__ void mma16816(float* c, const uint32_t* a, const uint32_t* b) {
    asm volatile(
        "mma.sync.aligned.m16n8k16.row.col.f32.bf16.bf16.f32 "
        "{%0,%1,%2,%3}, {%4,%5,%6,%7}, {%8,%9}, {%0,%1,%2,%3};"
        : "+f"(c[0]), "+f"(c[1]), "+f"(c[2]), "+f"(c[3])
        : "r"(a[0]), "r"(a[1]), "r"(a[2]), "r"(a[3]), "r"(b[0]), "r"(b[1]));
}
__device__ __forceinline__ uint32_t pack_bf16x2(float a, float b) {
    __nv_bfloat16 ha = __float2bfloat16(a), hb = __float2bfloat16(b);
    return (uint32_t)__bfloat16_as_ushort(ha) |
           ((uint32_t)__bfloat16_as_ushort(hb) << 16);
}

// ================= CSR build (4-launch prelude) ============================
__global__ void count_kernel(const int* __restrict__ ei, int* __restrict__ deg) {
    int e = blockIdx.x * blockDim.x + threadIdx.x;
    if (e < NEDGES) atomicAdd(&deg[ei[NEDGES + e]], 1);
}

// Single-pass scan: each block reduces all preceding degrees itself (<=12K
// int4 loads), then scans its own 1024-node chunk. Emits rowptr + cur.
__global__ __launch_bounds__(256) void scanall_kernel(
        const int* __restrict__ deg,
        int* __restrict__ rowptr, int* __restrict__ cur) {
    __shared__ int ws[8];
    __shared__ int pre;
    const int tid = threadIdx.x, lane = tid & 31, wid = tid >> 5;
    const int b = blockIdx.x;

    // ---- exclusive block offset: sum deg[0 .. b*1024) ----
    int off = 0;
    for (int i4 = tid; i4 < b * 256; i4 += 256) {
        int4 v = ((const int4*)deg)[i4];
        off += (v.x + v.y) + (v.z + v.w);
    }
    #pragma unroll
    for (int o = 16; o > 0; o >>= 1) off += __shfl_down_sync(~0u, off, o);
    if (lane == 0) ws[wid] = off;
    __syncthreads();
    if (wid == 0) {
        int t = (lane < 8) ? ws[lane] : 0;
        #pragma unroll
        for (int o = 4; o > 0; o >>= 1) t += __shfl_down_sync(~0u, t, o);
        if (lane == 0) pre = t;
    }
    __syncthreads();

    // ---- scan own chunk ----
    int i4 = b * 256 + tid;
    int4 v = make_int4(0, 0, 0, 0);
    if (i4 < NNODES / 4) v = ((const int4*)deg)[i4];
    int local = (v.x + v.y) + (v.z + v.w);
    int s = local;
    #pragma unroll
    for (int o = 1; o < 32; o <<= 1) {
        int t = __shfl_up_sync(~0u, s, o);
        if (lane >= o) s += t;
    }
    if (lane == 31) ws[wid] = s;
    __syncthreads();
    if (wid == 0) {
        int t = (lane < 8) ? ws[lane] : 0;
        #pragma unroll
        for (int o = 1; o < 8; o <<= 1) {
            int u = __shfl_up_sync(~0u, t, o);
            if (lane >= o) t += u;
        }
        if (lane < 8) ws[lane] = t;
    }
    __syncthreads();
    int excl = pre + (wid ? ws[wid - 1] : 0) + (s - local);
    if (i4 < NNODES / 4) {
        int idx = i4 * 4;
        int p0 = excl + v.x, p1 = p0 + v.y, p2 = p1 + v.z, p3 = p2 + v.w;
        cur[idx] = excl; cur[idx + 1] = p0; cur[idx + 2] = p1; cur[idx + 3] = p2;
        rowptr[idx + 1] = p0; rowptr[idx + 2] = p1;
        rowptr[idx + 3] = p2; rowptr[idx + 4] = p3;
    }
    if (b == 0 && tid == 0) rowptr[0] = 0;
}

__global__ void fill_kernel(const int* __restrict__ ei,
                            int* __restrict__ cur, int* __restrict__ col) {
    int e = blockIdx.x * blockDim.x + threadIdx.x;
    if (e >= NEDGES) return;
    int slot = atomicAdd(&cur[ei[NEDGES + e]], 1);
    col[slot] = ei[e];
}

// ==== W pre-split (W1/W2/Wc) + deg zeroing (kills the memset launch) ======
#define WSP_N1 (NLAYERS * 2 * HID * HID)
__global__ void wsplit_kernel(const float* __restrict__ W1,
                              const float* __restrict__ W2,
                              const float* __restrict__ Wc) {
    int i = blockIdx.x * blockDim.x + threadIdx.x;
    if (i < NNODES) g_deg[i] = 0;
    if (i < WSP_N1) {
        int e = i & (HID * HID - 1);
        int m = (i >> 14) & 1;           // 0 = W1, 1 = W2
        int l = i >> 15;                 // layer
        int k = e >> 7, n = e & 127;
        const float* W = (m ? W2 : W1) + (size_t)l * HID * HID;
        float v = W[k * HID + n];
        __nv_bfloat16 hi = __float2bfloat16(v);
        __nv_bfloat16 lo = __float2bfloat16(v - __bfloat162float(hi));
        __nv_bfloat16* base = g_wsp + ((size_t)l * 4 + m * 2) * HID * HID;
        base[n * HID + k] = hi;
        base[HID * HID + n * HID + k] = lo;
    } else {
        int j = i - WSP_N1;
        if (j >= OUTC * HID) return;
        int n = j / HID, k = j - n * HID;
        float v = Wc[k * OUTC + n];
        __nv_bfloat16 hi = __float2bfloat16(v);
        __nv_bfloat16 lo = __float2bfloat16(v - __bfloat162float(hi));
        g_wc[n * HID + k] = hi;
        g_wc[64 * HID + n * HID + k] = lo;
    }
}

// ===== gather: z[d,:] = h[d,:] + sum_{s in N(d)} h[s,:] -> split bf16 ======
// (8-way unroll — the R10 measured-best form)
__global__ __launch_bounds__(256) void gather_kernel(
        const float* __restrict__ h,
        const int* __restrict__ rowptr, const int* __restrict__ col) {
    int node = (blockIdx.x * blockDim.x + threadIdx.x) >> 5;
    if (node >= NNODES) return;
    int lane = threadIdx.x & 31;
    int beg = rowptr[node], end = rowptr[node + 1];
    float4 acc = *(const float4*)(h + (size_t)node * HID + lane * 4);
    int j = beg;
    while (j < end) {
        int n = min(32, end - j);
        int myc = (lane < n) ? col[j + lane] : 0;
        int t = 0;
        for (; t + 7 < n; t += 8) {
            float4 vv[8];
            #pragma unroll
            for (int u = 0; u < 8; u++) {
                int s = __shfl_sync(~0u, myc, t + u);
                vv[u] = *(const float4*)(h + (size_t)s * HID + lane * 4);
            }
            #pragma unroll
            for (int u = 0; u < 8; u++) {
                acc.x += vv[u].x; acc.y += vv[u].y;
                acc.z += vv[u].z; acc.w += vv[u].w;
            }
        }
        for (; t + 3 < n; t += 4) {
            float4 vv[4];
            #pragma unroll
            for (int u = 0; u < 4; u++) {
                int s = __shfl_sync(~0u, myc, t + u);
                vv[u] = *(const float4*)(h + (size_t)s * HID + lane * 4);
            }
            #pragma unroll
            for (int u = 0; u < 4; u++) {
                acc.x += vv[u].x; acc.y += vv[u].y;
                acc.z += vv[u].z; acc.w += vv[u].w;
            }
        }
        for (; t < n; t++) {
            int s = __shfl_sync(~0u, myc, t);
            float4 v = *(const float4*)(h + (size_t)s * HID + lane * 4);
            acc.x += v.x; acc.y += v.y; acc.z += v.z; acc.w += v.w;
        }
        j += n;
    }
    float f[4] = {acc.x, acc.y, acc.z, acc.w};
    uint32_t hw[2], lw[2];
    #pragma unroll
    for (int p = 0; p < 2; p++) {
        float v0 = f[2 * p], v1 = f[2 * p + 1];
        __nv_bfloat16 h0 = __float2bfloat16(v0), h1 = __float2bfloat16(v1);
        hw[p] = (uint32_t)__bfloat16_as_ushort(h0) |
                ((uint32_t)__bfloat16_as_ushort(h1) << 16);
        lw[p] = pack_bf16x2(v0 - __bfloat162float(h0), v1 - __bfloat162float(h1));
    }
    size_t off = (size_t)node * HID + lane * 4;   // bf16 elements
    *(uint2*)((char*)g_zhi + off * 2) = make_uint2(hw[0], hw[1]);
    *(uint2*)((char*)g_zlo + off * 2) = make_uint2(lw[0], lw[1]);
}

// ===================== tensor-core fused GIN MLP (mma.sync) ================
// 512 threads, 16 warps: warp (mwarp, nhalf) owns 16 rows x 64 cols.
// SMEM rows padded to 272B (17 x 16B) -> ldmatrix conflict-free.
// Layout: Ahi, Alo, B1hi, B1lo, B2hi, B2lo (6 x 34816B) + biases.
#define SROW 272
#define ATB  (128 * SROW)
#define MLP_SMEM (6 * ATB + 1536)

__device__ __forceinline__ void stage_mat(char* dst, const uint4* src,
                                          int tid, int nrow) {
    for (int i = tid; i < nrow * 16; i += 512) {
        int row = i >> 4, ch = i & 15;
        *(uint4*)(dst + row * SROW + ch * 16) = src[i];
    }
}

// One GEMM phase over this warp's n-range: acc += 3 split terms.
template <int NJP>
__device__ __forceinline__ void phase(float (*acc)[4], uint32_t aA, uint32_t aB) {
    #pragma unroll 1
    for (int t = 0; t < 3; t++) {
        uint32_t aa = aA + ((t == 2) ? ATB : 0);
        uint32_t bb = aB + ((t == 1) ? ATB : 0);
        #pragma unroll
        for (int kc = 0; kc < 8; kc++) {
            uint32_t a[4];
            ldsm_x4(a, aa + kc * 32);
            #pragma unroll
            for (int jp = 0; jp < NJP; jp++) {
                uint32_t b[4];
                ldsm_x4(b, bb + jp * 16 * SROW + kc * 32);
                mma16816(acc[2 * jp],     a, b);
                mma16816(acc[2 * jp + 1], a, b + 2);
            }
        }
    }
}

// relu + hi/lo split of acc back into the A tiles (warp's 16 rows x 64 cols).
__device__ __forceinline__ void epi_to_smem(float (*acc)[4], char* ah, char* al,
                                            int mwarp, int lane, int nhalf) {
    int rl = lane >> 2;
    int rowL = mwarp * 16 + rl, rowH = rowL + 8;
    #pragma unroll
    for (int j = 0; j < 8; j++) {
        int boff = nhalf * 128 + 16 * j + (lane & 3) * 4;
        float v0 = fmaxf(acc[j][0], 0.f), v1 = fmaxf(acc[j][1], 0.f);
        float v2 = fmaxf(acc[j][2], 0.f), v3 = fmaxf(acc[j][3], 0.f);
        __nv_bfloat16 h0 = __float2bfloat16(v0), h1 = __float2bfloat16(v1);
        __nv_bfloat16 h2 = __float2bfloat16(v2), h3 = __float2bfloat16(v3);
        *(uint32_t*)(ah + rowL * SROW + boff) =
            (uint32_t)__bfloat16_as_ushort(h0) |
            ((uint32_t)__bfloat16_as_ushort(h1) << 16);
        *(uint32_t*)(ah + rowH * SROW + boff) =
            (uint32_t)__bfloat16_as_ushort(h2) |
            ((uint32_t)__bfloat16_as_ushort(h3) << 16);
        *(uint32_t*)(al + rowL * SROW + boff) =
            pack_bf16x2(v0 - __bfloat162float(h0), v1 - __bfloat162float(h1));
        *(uint32_t*)(al + rowH * SROW + boff) =
            pack_bf16x2(v2 - __bfloat162float(h2), v3 - __bfloat162float(h3));
    }
}

__global__ __launch_bounds__(512) void mlp_mma_kernel(
        float* __restrict__ hout, int layer, int last,
        const float* __restrict__ b1, const float* __restrict__ b2,
        const float* __restrict__ bc, float* __restrict__ out) {
    extern __shared__ char sm[];
    char* ah = sm;
    char* al = sm + ATB;
    char* b1h = sm + 2 * ATB;          // also Wc slot for last layer
    char* b2h = sm + 4 * ATB;
    float* bs1 = (float*)(sm + 6 * ATB);
    float* bs2 = bs1 + HID;
    float* bs3 = bs2 + HID;            // 64 floats (bc padded)

    const int tid = threadIdx.x;
    const int warp = tid >> 5, lane = tid & 31;
    const int mwarp = warp & 7;        // row group (16 rows)
    const int nhalf = warp >> 3;       // column half (64 cols)
    const int tile = blockIdx.x;
    const int row0 = tile * 128;
    const int rmax = NNODES - row0;

    // ---- stage A (split z) + W1^T + W2^T (split) + biases ----
    stage_mat(ah,  (const uint4*)((const char*)g_zhi + (size_t)tile * 32768), tid, 128);
    stage_mat(al,  (const uint4*)((const char*)g_zlo + (size_t)tile * 32768), tid, 128);
    stage_mat(b1h, (const uint4*)(g_wsp + ((size_t)layer * 4 + 0) * HID * HID), tid, 128);
    stage_mat(b1h + ATB, (const uint4*)(g_wsp + ((size_t)layer * 4 + 1) * HID * HID), tid, 128);
    stage_mat(b2h, (const uint4*)(g_wsp + ((size_t)layer * 4 + 2) * HID * HID), tid, 128);
    stage_mat(b2h + ATB, (const uint4*)(g_wsp + ((size_t)layer * 4 + 3) * HID * HID), tid, 128);
    if (tid < HID) { bs1[tid] = b1[tid]; bs2[tid] = b2[tid]; }
    if (tid < 64)  bs3[tid] = (tid < OUTC) ? bc[tid] : 0.f;
    __syncthreads();

    // ldmatrix lane addressing
    const int rr = lane & 7, g = lane >> 3;
    const uint32_t aA = smem_u32(ah) +
        (mwarp * 16 + (g & 1) * 8 + rr) * SROW + (g >> 1) * 16;
    const uint32_t bOff = ((g >> 1) * 8 + rr) * SROW + (g & 1) * 16;
    const uint32_t aB1 = smem_u32(b1h) + bOff + nhalf * 64 * SROW;
    const uint32_t aB2 = smem_u32(b2h) + bOff + nhalf * 64 * SROW;

    const int cl = (lane & 3) * 2;
    const int rl = lane >> 2;

    float acc[8][4];

    // ---- phase 1: hidden = relu(z @ W1 + b1) ----
    #pragma unroll
    for (int j = 0; j < 8; j++) {
        int c = nhalf * 64 + 8 * j + cl;
        float v0 = bs1[c], v1 = bs1[c + 1];
        acc[j][0] = v0; acc[j][1] = v1; acc[j][2] = v0; acc[j][3] = v1;
    }
    phase<4>(acc, aA, aB1);
    epi_to_smem(acc, ah, al, mwarp, lane, nhalf);
    __syncthreads();                     // both col-halves of A rows complete

    if (last) {                          // overwrite B1 slots with Wc (split)
        stage_mat(b1h, (const uint4*)g_wc, tid, 64);
        stage_mat(b1h + ATB, (const uint4*)(g_wc + 64 * HID), tid, 64);
        __syncthreads();
    }

    // ---- phase 2: hfin = relu(hidden @ W2 + b2) ----
    #pragma unroll
    for (int j = 0; j < 8; j++) {
        int c = nhalf * 64 + 8 * j + cl;
        float v0 = bs2[c], v1 = bs2[c + 1];
        acc[j][0] = v0; acc[j][1] = v1; acc[j][2] = v0; acc[j][3] = v1;
    }
    phase<4>(acc, aA, aB2);

    if (!last) {
        // epilogue: relu -> hout fp32 (warp's 16 rows x 64 cols)
        int rowL = mwarp * 16 + rl, rowH = rowL + 8;
        bool okL = rowL < rmax, okH = rowH < rmax;
        #pragma unroll
        for (int j = 0; j < 8; j++) {
            int c = nhalf * 64 + 8 * j + cl;
            if (okL) {
                float2 o = make_float2(fmaxf(acc[j][0], 0.f), fmaxf(acc[j][1], 0.f));
                *(float2*)(hout + (size_t)(row0 + rowL) * HID + c) = o;
            }
            if (okH) {
                float2 o = make_float2(fmaxf(acc[j][2], 0.f), fmaxf(acc[j][3], 0.f));
                *(float2*)(hout + (size_t)(row0 + rowH) * HID + c) = o;
            }
        }
        return;
    }

    // ---- last layer: keep hfin in SMEM, fused classifier phase ----
    epi_to_smem(acc, ah, al, mwarp, lane, nhalf);
    __syncthreads();

    float acc3[4][4];
    #pragma unroll
    for (int j = 0; j < 4; j++) {
        int c = nhalf * 32 + 8 * j + cl;
        float v0 = bs3[c], v1 = bs3[c + 1];
        acc3[j][0] = v0; acc3[j][1] = v1; acc3[j][2] = v0; acc3[j][3] = v1;
    }
    // B1 slots hold Wc (64 n-rows); warp covers n in [nhalf*32, nhalf*32+32)
    phase<2>(acc3, aA, smem_u32(b1h) + bOff + nhalf * 32 * SROW);

    {
        int rowL = mwarp * 16 + rl, rowH = rowL + 8;
        bool okL = rowL < rmax, okH = rowH < rmax;
        int jmax = nhalf ? 1 : 4;        // cols 0..31 | 32..39 (OUTC=40)
        for (int j = 0; j < jmax; j++) {
            int c = nhalf * 32 + 8 * j + cl;
            if (okL) {
                float2 o = make_float2(acc3[j][0], acc3[j][1]);
                *(float2*)(out + (size_t)(row0 + rowL) * OUTC + c) = o;
            }
            if (okH) {
                float2 o = make_float2(acc3[j][2], acc3[j][3]);
                *(float2*)(out + (size_t)(row0 + rowH) * OUTC + c) = o;
            }
        }
    }
}

// ---------------- launch ----------------
extern "C" void kernel_launch(void* const* d_in, const int* in_sizes, int n_in,
                              void* d_out, int out_size) {
    (void)in_sizes; (void)n_in; (void)out_size;
    const float* x  = (const float*)d_in[0];
    const int*   ei = (const int*)d_in[2];       // int32 (JAX demotes int64)
    const float* W1 = (const float*)d_in[3];
    const float* b1 = (const float*)d_in[4];
    const float* W2 = (const float*)d_in[5];
    const float* b2 = (const float*)d_in[6];
    const float* Wc = (const float*)d_in[7];
    const float* bc = (const float*)d_in[8];
    float* out = (float*)d_out;

    float* hbuf;
    int *deg, *rowptr, *cur, *col;
    cudaGetSymbolAddress((void**)&hbuf, g_h);
    cudaGetSymbolAddress((void**)&deg, g_deg);
    cudaGetSymbolAddress((void**)&rowptr, g_rowptr);
    cudaGetSymbolAddress((void**)&cur, g_cur);
    cudaGetSymbolAddress((void**)&col, g_col);

    cudaFuncSetAttribute(mlp_mma_kernel,
                         cudaFuncAttributeMaxDynamicSharedMemorySize, MLP_SMEM);

    const int EB = (NEDGES + 255) / 256;
    const int GB = (NNODES * 32 + 255) / 256;
    const int WB = (WSP_N1 + OUTC * HID + 255) / 256;

    // 4-launch prelude: wsplit(+deg zero), count, scanall, fill
    wsplit_kernel<<<WB, 256>>>(W1, W2, Wc);
    count_kernel<<<EB, 256>>>(ei, deg);
    scanall_kernel<<<SCB, 256>>>(deg, rowptr, cur);
    fill_kernel<<<EB, 256>>>(ei, cur, col);

    // layer 0 (h = x); first gather is launch #5 -> ncu capture target
    gather_kernel<<<GB, 256>>>(x, rowptr, col);
    mlp_mma_kernel<<<NTILES, 512, MLP_SMEM>>>(hbuf, 0, 0, b1, b2, bc, out);

    for (int l = 1; l < NLAYERS; l++) {
        gather_kernel<<<GB, 256>>>(hbuf, rowptr, col);
        mlp_mma_kernel<<<NTILES, 512, MLP_SMEM>>>(
            hbuf, l, (l == NLAYERS - 1) ? 1 : 0,
            b1 + (size_t)l * HID, b2 + (size_t)l * HID, bc, out);
    }
}

// round 15
// speedup vs baseline: 1.2448x; 1.2448x over previous
#include <cuda_runtime.h>
#include <cuda_bf16.h>
#include <stdint.h>

#define NNODES  50000
#define HID     128
#define NEDGES  600000
#define OUTC    40
#define NLAYERS 3
#define NTILES  391            // ceil(50000/128)
#define SCB     49             // ceil(50000/1024) scan blocks

// ---------------- persistent scratch (__device__ globals, zero-init) -------
__device__ float g_h[(size_t)NNODES * HID];
__device__ __nv_bfloat16 g_zhi[(size_t)NTILES * 128 * HID];   // row-major split z
__device__ __nv_bfloat16 g_zlo[(size_t)NTILES * 128 * HID];
// per layer: [W1hi, W1lo, W2hi, W2lo], each W^T [n][k] row-major 128x128 bf16
__device__ __nv_bfloat16 g_wsp[(size_t)NLAYERS * 4 * HID * HID];
// Wc^T padded to [64][128], hi then lo (pad rows never written -> stay zero)
__device__ __nv_bfloat16 g_wc[2 * 64 * HID];
__device__ int g_deg[NNODES];
__device__ int g_rowptr[NNODES + 1];
__device__ int g_cur[NNODES];
__device__ int g_col[NEDGES];

// ---------------- mma.sync / ldmatrix (sm_80+ baseline, non-'a') -----------
__device__ __forceinline__ uint32_t smem_u32(const void* p) {
    uint32_t a;
    asm("{ .reg .u64 t; cvta.to.shared.u64 t, %1; cvt.u32.u64 %0, t; }"
        : "=r"(a) : "l"(p));
    return a;
}
__device__ __forceinline__ void ldsm_x4(uint32_t* r, uint32_t addr) {
    asm volatile("ldmatrix.sync.aligned.m8n8.x4.shared.b16 {%0,%1,%2,%3}, [%4];"
                 : "=r"(r[0]), "=r"(r[1]), "=r"(r[2]), "=r"(r[3]) : "r"(addr));
}
__device__ __forceinline__ void mma16816(float* c, const uint32_t* a, const uint32_t* b) {
    asm volatile(
        "mma.sync.aligned.m16n8k16.row.col.f32.bf16.bf16.f32 "
        "{%0,%1,%2,%3}, {%4,%5,%6,%7}, {%8,%9}, {%0,%1,%2,%3};"
        : "+f"(c[0]), "+f"(c[1]), "+f"(c[2]), "+f"(c[3])
        : "r"(a[0]), "r"(a[1]), "r"(a[2]), "r"(a[3]), "r"(b[0]), "r"(b[1]));
}
__device__ __forceinline__ uint32_t pack_bf16x2(float a, float b) {
    __nv_bfloat16 ha = __float2bfloat16(a), hb = __float2bfloat16(b);
    return (uint32_t)__bfloat16_as_ushort(ha) |
           ((uint32_t)__bfloat16_as_ushort(hb) << 16);
}

// ================= CSR build (4-launch prelude) ============================
__global__ void count_kernel(const int* __restrict__ ei, int* __restrict__ deg) {
    int e = blockIdx.x * blockDim.x + threadIdx.x;
    if (e < NEDGES) atomicAdd(&deg[ei[NEDGES + e]], 1);
}

// Single-pass scan: each block reduces all preceding degrees itself (<=12K
// int4 loads), then scans its own 1024-node chunk. Emits rowptr + cur.
__global__ __launch_bounds__(256) void scanall_kernel(
        const int* __restrict__ deg,
        int* __restrict__ rowptr, int* __restrict__ cur) {
    __shared__ int ws[8];
    __shared__ int pre;
    const int tid = threadIdx.x, lane = tid & 31, wid = tid >> 5;
    const int b = blockIdx.x;

    // ---- exclusive block offset: sum deg[0 .. b*1024) ----
    int off = 0;
    for (int i4 = tid; i4 < b * 256; i4 += 256) {
        int4 v = ((const int4*)deg)[i4];
        off += (v.x + v.y) + (v.z + v.w);
    }
    #pragma unroll
    for (int o = 16; o > 0; o >>= 1) off += __shfl_down_sync(~0u, off, o);
    if (lane == 0) ws[wid] = off;
    __syncthreads();
    if (wid == 0) {
        int t = (lane < 8) ? ws[lane] : 0;
        #pragma unroll
        for (int o = 4; o > 0; o >>= 1) t += __shfl_down_sync(~0u, t, o);
        if (lane == 0) pre = t;
    }
    __syncthreads();

    // ---- scan own chunk ----
    int i4 = b * 256 + tid;
    int4 v = make_int4(0, 0, 0, 0);
    if (i4 < NNODES / 4) v = ((const int4*)deg)[i4];
    int local = (v.x + v.y) + (v.z + v.w);
    int s = local;
    #pragma unroll
    for (int o = 1; o < 32; o <<= 1) {
        int t = __shfl_up_sync(~0u, s, o);
        if (lane >= o) s += t;
    }
    if (lane == 31) ws[wid] = s;
    __syncthreads();
    if (wid == 0) {
        int t = (lane < 8) ? ws[lane] : 0;
        #pragma unroll
        for (int o = 1; o < 8; o <<= 1) {
            int u = __shfl_up_sync(~0u, t, o);
            if (lane >= o) t += u;
        }
        if (lane < 8) ws[lane] = t;
    }
    __syncthreads();
    int excl = pre + (wid ? ws[wid - 1] : 0) + (s - local);
    if (i4 < NNODES / 4) {
        int idx = i4 * 4;
        int p0 = excl + v.x, p1 = p0 + v.y, p2 = p1 + v.z, p3 = p2 + v.w;
        cur[idx] = excl; cur[idx + 1] = p0; cur[idx + 2] = p1; cur[idx + 3] = p2;
        rowptr[idx + 1] = p0; rowptr[idx + 2] = p1;
        rowptr[idx + 3] = p2; rowptr[idx + 4] = p3;
    }
    if (b == 0 && tid == 0) rowptr[0] = 0;
}

__global__ void fill_kernel(const int* __restrict__ ei,
                            int* __restrict__ cur, int* __restrict__ col) {
    int e = blockIdx.x * blockDim.x + threadIdx.x;
    if (e >= NEDGES) return;
    int slot = atomicAdd(&cur[ei[NEDGES + e]], 1);
    col[slot] = ei[e];
}

// ==== W pre-split (W1/W2/Wc) + deg zeroing (kills the memset launch) ======
#define WSP_N1 (NLAYERS * 2 * HID * HID)
__global__ void wsplit_kernel(const float* __restrict__ W1,
                              const float* __restrict__ W2,
                              const float* __restrict__ Wc) {
    int i = blockIdx.x * blockDim.x + threadIdx.x;
    if (i < NNODES) g_deg[i] = 0;
    if (i < WSP_N1) {
        int e = i & (HID * HID - 1);
        int m = (i >> 14) & 1;           // 0 = W1, 1 = W2
        int l = i >> 15;                 // layer
        int k = e >> 7, n = e & 127;
        const float* W = (m ? W2 : W1) + (size_t)l * HID * HID;
        float v = W[k * HID + n];
        __nv_bfloat16 hi = __float2bfloat16(v);
        __nv_bfloat16 lo = __float2bfloat16(v - __bfloat162float(hi));
        __nv_bfloat16* base = g_wsp + ((size_t)l * 4 + m * 2) * HID * HID;
        base[n * HID + k] = hi;
        base[HID * HID + n * HID + k] = lo;
    } else {
        int j = i - WSP_N1;
        if (j >= OUTC * HID) return;
        int n = j / HID, k = j - n * HID;
        float v = Wc[k * OUTC + n];
        __nv_bfloat16 hi = __float2bfloat16(v);
        __nv_bfloat16 lo = __float2bfloat16(v - __bfloat162float(hi));
        g_wc[n * HID + k] = hi;
        g_wc[64 * HID + n * HID + k] = lo;
    }
}

// ===== gather: z[d,:] = h[d,:] + sum_{s in N(d)} h[s,:] -> split bf16 ======
// (8-way unroll — the R10 measured-best form)
__global__ __launch_bounds__(256) void gather_kernel(
        const float* __restrict__ h,
        const int* __restrict__ rowptr, const int* __restrict__ col) {
    int node = (blockIdx.x * blockDim.x + threadIdx.x) >> 5;
    if (node >= NNODES) return;
    int lane = threadIdx.x & 31;
    int beg = rowptr[node], end = rowptr[node + 1];
    float4 acc = *(const float4*)(h + (size_t)node * HID + lane * 4);
    int j = beg;
    while (j < end) {
        int n = min(32, end - j);
        int myc = (lane < n) ? col[j + lane] : 0;
        int t = 0;
        for (; t + 7 < n; t += 8) {
            float4 vv[8];
            #pragma unroll
            for (int u = 0; u < 8; u++) {
                int s = __shfl_sync(~0u, myc, t + u);
                vv[u] = *(const float4*)(h + (size_t)s * HID + lane * 4);
            }
            #pragma unroll
            for (int u = 0; u < 8; u++) {
                acc.x += vv[u].x; acc.y += vv[u].y;
                acc.z += vv[u].z; acc.w += vv[u].w;
            }
        }
        for (; t + 3 < n; t += 4) {
            float4 vv[4];
            #pragma unroll
            for (int u = 0; u < 4; u++) {
                int s = __shfl_sync(~0u, myc, t + u);
                vv[u] = *(const float4*)(h + (size_t)s * HID + lane * 4);
            }
            #pragma unroll
            for (int u = 0; u < 4; u++) {
                acc.x += vv[u].x; acc.y += vv[u].y;
                acc.z += vv[u].z; acc.w += vv[u].w;
            }
        }
        for (; t < n; t++) {
            int s = __shfl_sync(~0u, myc, t);
            float4 v = *(const float4*)(h + (size_t)s * HID + lane * 4);
            acc.x += v.x; acc.y += v.y; acc.z += v.z; acc.w += v.w;
        }
        j += n;
    }
    float f[4] = {acc.x, acc.y, acc.z, acc.w};
    uint32_t hw[2], lw[2];
    #pragma unroll
    for (int p = 0; p < 2; p++) {
        float v0 = f[2 * p], v1 = f[2 * p + 1];
        __nv_bfloat16 h0 = __float2bfloat16(v0), h1 = __float2bfloat16(v1);
        hw[p] = (uint32_t)__bfloat16_as_ushort(h0) |
                ((uint32_t)__bfloat16_as_ushort(h1) << 16);
        lw[p] = pack_bf16x2(v0 - __bfloat162float(h0), v1 - __bfloat162float(h1));
    }
    size_t off = (size_t)node * HID + lane * 4;   // bf16 elements
    *(uint2*)((char*)g_zhi + off * 2) = make_uint2(hw[0], hw[1]);
    *(uint2*)((char*)g_zlo + off * 2) = make_uint2(lw[0], lw[1]);
}

// ===================== tensor-core fused GIN MLP (mma.sync) ================
// 256 threads / 8 warps, warp owns 16 rows x full 128 cols (measured-best).
// SMEM rows padded to 272B (17 x 16B) -> ldmatrix conflict-free.
// Layout: Ahi, Alo, B1hi, B1lo, B2hi, B2lo (6 x 34816B) + biases.
#define SROW 272
#define ATB  (128 * SROW)
#define MLP_SMEM (6 * ATB + 1536)

__device__ __forceinline__ void stage_mat(char* dst, const uint4* src,
                                          int tid, int nrow) {
    for (int i = tid; i < nrow * 16; i += 256) {
        int row = i >> 4, ch = i & 15;
        *(uint4*)(dst + row * SROW + ch * 16) = src[i];
    }
}

// One GEMM phase: acc += Ahi*Bhi + Ahi*Blo + Alo*Bhi (split terms).
template <int NJP>
__device__ __forceinline__ void phase(float (*acc)[4], uint32_t aA, uint32_t aB) {
    #pragma unroll 1
    for (int t = 0; t < 3; t++) {
        uint32_t aa = aA + ((t == 2) ? ATB : 0);
        uint32_t bb = aB + ((t == 1) ? ATB : 0);
        #pragma unroll
        for (int kc = 0; kc < 8; kc++) {
            uint32_t a[4];
            ldsm_x4(a, aa + kc * 32);
            #pragma unroll
            for (int jp = 0; jp < NJP; jp++) {
                uint32_t b[4];
                ldsm_x4(b, bb + jp * 16 * SROW + kc * 32);
                mma16816(acc[2 * jp],     a, b);
                mma16816(acc[2 * jp + 1], a, b + 2);
            }
        }
    }
}

// relu + hi/lo split of acc back into the A tiles (warp-local rows).
__device__ __forceinline__ void epi_to_smem(float (*acc)[4], char* ah, char* al,
                                            int warp, int lane) {
    int rl = lane >> 2;
    int rowL = warp * 16 + rl, rowH = rowL + 8;
    #pragma unroll
    for (int j = 0; j < 16; j++) {
        int boff = 16 * j + (lane & 3) * 4;
        float v0 = fmaxf(acc[j][0], 0.f), v1 = fmaxf(acc[j][1], 0.f);
        float v2 = fmaxf(acc[j][2], 0.f), v3 = fmaxf(acc[j][3], 0.f);
        __nv_bfloat16 h0 = __float2bfloat16(v0), h1 = __float2bfloat16(v1);
        __nv_bfloat16 h2 = __float2bfloat16(v2), h3 = __float2bfloat16(v3);
        *(uint32_t*)(ah + rowL * SROW + boff) =
            (uint32_t)__bfloat16_as_ushort(h0) |
            ((uint32_t)__bfloat16_as_ushort(h1) << 16);
        *(uint32_t*)(ah + rowH * SROW + boff) =
            (uint32_t)__bfloat16_as_ushort(h2) |
            ((uint32_t)__bfloat16_as_ushort(h3) << 16);
        *(uint32_t*)(al + rowL * SROW + boff) =
            pack_bf16x2(v0 - __bfloat162float(h0), v1 - __bfloat162float(h1));
        *(uint32_t*)(al + rowH * SROW + boff) =
            pack_bf16x2(v2 - __bfloat162float(h2), v3 - __bfloat162float(h3));
    }
}

__global__ __launch_bounds__(256) void mlp_mma_kernel(
        float* __restrict__ hout, int layer, int last,
        const float* __restrict__ b1, const float* __restrict__ b2,
        const float* __restrict__ bc, float* __restrict__ out) {
    extern __shared__ char sm[];
    char* ah = sm;
    char* al = sm + ATB;
    char* b1h = sm + 2 * ATB;          // also Wc slot for last layer
    char* b2h = sm + 4 * ATB;
    float* bs1 = (float*)(sm + 6 * ATB);
    float* bs2 = bs1 + HID;
    float* bs3 = bs2 + HID;            // 64 floats (bc padded)

    const int tid = threadIdx.x;
    const int warp = tid >> 5, lane = tid & 31;
    const int tile = blockIdx.x;
    const int row0 = tile * 128;
    const int rmax = NNODES - row0;

    // ---- stage A (split z) + W1^T + W2^T (split) + biases ----
    stage_mat(ah,  (const uint4*)((const char*)g_zhi + (size_t)tile * 32768), tid, 128);
    stage_mat(al,  (const uint4*)((const char*)g_zlo + (size_t)tile * 32768), tid, 128);
    stage_mat(b1h, (const uint4*)(g_wsp + ((size_t)layer * 4 + 0) * HID * HID), tid, 128);
    stage_mat(b1h + ATB, (const uint4*)(g_wsp + ((size_t)layer * 4 + 1) * HID * HID), tid, 128);
    stage_mat(b2h, (const uint4*)(g_wsp + ((size_t)layer * 4 + 2) * HID * HID), tid, 128);
    stage_mat(b2h + ATB, (const uint4*)(g_wsp + ((size_t)layer * 4 + 3) * HID * HID), tid, 128);
    if (tid < HID) { bs1[tid] = b1[tid]; bs2[tid] = b2[tid]; }
    if (tid < 64)  bs3[tid] = (tid < OUTC) ? bc[tid] : 0.f;
    __syncthreads();

    // ldmatrix lane addressing
    const int rr = lane & 7, g = lane >> 3;
    const uint32_t aA = smem_u32(ah) +
        (warp * 16 + (g & 1) * 8 + rr) * SROW + (g >> 1) * 16;
    const uint32_t bOff = ((g >> 1) * 8 + rr) * SROW + (g & 1) * 16;
    const uint32_t aB1 = smem_u32(b1h) + bOff;
    const uint32_t aB2 = smem_u32(b2h) + bOff;

    const int cl = (lane & 3) * 2;
    const int rl = lane >> 2;

    float acc[16][4];

    // ---- phase 1: hidden = relu(z @ W1 + b1) ----
    #pragma unroll
    for (int j = 0; j < 16; j++) {
        float v0 = bs1[8 * j + cl], v1 = bs1[8 * j + cl + 1];
        acc[j][0] = v0; acc[j][1] = v1; acc[j][2] = v0; acc[j][3] = v1;
    }
    phase<8>(acc, aA, aB1);
    epi_to_smem(acc, ah, al, warp, lane);   // warp-local rows only

    if (last) {
        __syncthreads();                     // phase-1 B1 reads done everywhere
        stage_mat(b1h, (const uint4*)g_wc, tid, 64);            // Wc hi
        stage_mat(b1h + ATB, (const uint4*)(g_wc + 64 * HID), tid, 64);  // Wc lo
        __syncthreads();
    } else {
        __syncwarp();                        // A rewrite is warp-local; B2 untouched
    }

    // ---- phase 2: hfin = relu(hidden @ W2 + b2) ----
    #pragma unroll
    for (int j = 0; j < 16; j++) {
        float v0 = bs2[8 * j + cl], v1 = bs2[8 * j + cl + 1];
        acc[j][0] = v0; acc[j][1] = v1; acc[j][2] = v0; acc[j][3] = v1;
    }
    phase<8>(acc, aA, aB2);

    if (!last) {
        // epilogue: relu -> hout fp32
        int rowL = warp * 16 + rl, rowH = rowL + 8;
        bool okL = rowL < rmax, okH = rowH < rmax;
        #pragma unroll
        for (int j = 0; j < 16; j++) {
            int c = 8 * j + cl;
            if (okL) {
                float2 o = make_float2(fmaxf(acc[j][0], 0.f), fmaxf(acc[j][1], 0.f));
                *(float2*)(hout + (size_t)(row0 + rowL) * HID + c) = o;
            }
            if (okH) {
                float2 o = make_float2(fmaxf(acc[j][2], 0.f), fmaxf(acc[j][3], 0.f));
                *(float2*)(hout + (size_t)(row0 + rowH) * HID + c) = o;
            }
        }
        return;
    }

    // ---- last layer: keep hfin in SMEM, fused classifier phase ----
    epi_to_smem(acc, ah, al, warp, lane);
    __syncwarp();

    float acc3[8][4];
    #pragma unroll
    for (int j = 0; j < 8; j++) {
        float v0 = bs3[8 * j + cl], v1 = bs3[8 * j + cl + 1];
        acc3[j][0] = v0; acc3[j][1] = v1; acc3[j][2] = v0; acc3[j][3] = v1;
    }
    phase<4>(acc3, aA, aB1);   // B1 slots now hold Wc (split), n = 64

    {
        int rowL = warp * 16 + rl, rowH = rowL + 8;
        bool okL = rowL < rmax, okH = rowH < rmax;
        #pragma unroll
        for (int j = 0; j < 5; j++) {        // cols 0..39 (pairs up to 38/39)
            int c = 8 * j + cl;
            if (okL) {
                float2 o = make_float2(acc3[j][0], acc3[j][1]);
                *(float2*)(out + (size_t)(row0 + rowL) * OUTC + c) = o;
            }
            if (okH) {
                float2 o = make_float2(acc3[j][2], acc3[j][3]);
                *(float2*)(out + (size_t)(row0 + rowH) * OUTC + c) = o;
            }
        }
    }
}

// ---------------- launch ----------------
extern "C" void kernel_launch(void* const* d_in, const int* in_sizes, int n_in,
                              void* d_out, int out_size) {
    (void)in_sizes; (void)n_in; (void)out_size;
    const float* x  = (const float*)d_in[0];
    const int*   ei = (const int*)d_in[2];       // int32 (JAX demotes int64)
    const float* W1 = (const float*)d_in[3];
    const float* b1 = (const float*)d_in[4];
    const float* W2 = (const float*)d_in[5];
    const float* b2 = (const float*)d_in[6];
    const float* Wc = (const float*)d_in[7];
    const float* bc = (const float*)d_in[8];
    float* out = (float*)d_out;

    float* hbuf;
    int *deg, *rowptr, *cur, *col;
    cudaGetSymbolAddress((void**)&hbuf, g_h);
    cudaGetSymbolAddress((void**)&deg, g_deg);
    cudaGetSymbolAddress((void**)&rowptr, g_rowptr);
    cudaGetSymbolAddress((void**)&cur, g_cur);
    cudaGetSymbolAddress((void**)&col, g_col);

    cudaFuncSetAttribute(mlp_mma_kernel,
                         cudaFuncAttributeMaxDynamicSharedMemorySize, MLP_SMEM);

    const int EB = (NEDGES + 255) / 256;
    const int GB = (NNODES * 32 + 255) / 256;
    const int WB = (WSP_N1 + OUTC * HID + 255) / 256;

    // 4-launch prelude: wsplit(+deg zero), count, scanall, fill
    wsplit_kernel<<<WB, 256>>>(W1, W2, Wc);
    count_kernel<<<EB, 256>>>(ei, deg);
    scanall_kernel<<<SCB, 256>>>(deg, rowptr, cur);
    fill_kernel<<<EB, 256>>>(ei, cur, col);

    // layer 0 (h = x)
    gather_kernel<<<GB, 256>>>(x, rowptr, col);
    mlp_mma_kernel<<<NTILES, 256, MLP_SMEM>>>(hbuf, 0, 0, b1, b2, bc, out);

    for (int l = 1; l < NLAYERS; l++) {
        gather_kernel<<<GB, 256>>>(hbuf, rowptr, col);
        mlp_mma_kernel<<<NTILES, 256, MLP_SMEM>>>(
            hbuf, l, (l == NLAYERS - 1) ? 1 : 0,
            b1 + (size_t)l * HID, b2 + (size_t)l * HID, bc, out);
    }
}

// round 17
// speedup vs baseline: 1.2606x; 1.0127x over previous
#include <cuda_runtime.h>
#include <cuda_bf16.h>
#include <stdint.h>

#define NNODES  50000
#define HID     128
#define NEDGES  600000
#define OUTC    40
#define NLAYERS 3
#define NTILES  391            // ceil(50000/128)
#define SCB     49             // ceil(50000/1024) scan blocks

// ---------------- persistent scratch (__device__ globals, zero-init) -------
__device__ float g_h[(size_t)NNODES * HID];
__device__ __nv_bfloat16 g_zhi[(size_t)NTILES * 128 * HID];   // row-major split z
__device__ __nv_bfloat16 g_zlo[(size_t)NTILES * 128 * HID];
// per layer: [W1hi, W1lo, W2hi, W2lo], each W^T [n][k] row-major 128x128 bf16
__device__ __nv_bfloat16 g_wsp[(size_t)NLAYERS * 4 * HID * HID];
// Wc^T padded to [64][128], hi then lo (pad rows never written -> stay zero)
__device__ __nv_bfloat16 g_wc[2 * 64 * HID];
__device__ int g_deg[NNODES];
__device__ int g_rowptr[NNODES + 1];
__device__ int g_cur[NNODES];
__device__ int g_col[NEDGES];

// ---------------- mma.sync / ldmatrix (sm_80+ baseline, non-'a') -----------
__device__ __forceinline__ uint32_t smem_u32(const void* p) {
    uint32_t a;
    asm("{ .reg .u64 t; cvta.to.shared.u64 t, %1; cvt.u32.u64 %0, t; }"
        : "=r"(a) : "l"(p));
    return a;
}
__device__ __forceinline__ void ldsm_x4(uint32_t* r, uint32_t addr) {
    asm volatile("ldmatrix.sync.aligned.m8n8.x4.shared.b16 {%0,%1,%2,%3}, [%4];"
                 : "=r"(r[0]), "=r"(r[1]), "=r"(r[2]), "=r"(r[3]) : "r"(addr));
}
__device__ __forceinline__ void mma16816(float* c, const uint32_t* a, const uint32_t* b) {
    asm volatile(
        "mma.sync.aligned.m16n8k16.row.col.f32.bf16.bf16.f32 "
        "{%0,%1,%2,%3}, {%4,%5,%6,%7}, {%8,%9}, {%0,%1,%2,%3};"
        : "+f"(c[0]), "+f"(c[1]), "+f"(c[2]), "+f"(c[3])
        : "r"(a[0]), "r"(a[1]), "r"(a[2]), "r"(a[3]), "r"(b[0]), "r"(b[1]));
}
__device__ __forceinline__ uint32_t pack_bf16x2(float a, float b) {
    __nv_bfloat16 ha = __float2bfloat16(a), hb = __float2bfloat16(b);
    return (uint32_t)__bfloat16_as_ushort(ha) |
           ((uint32_t)__bfloat16_as_ushort(hb) << 16);
}

// ================= CSR build (4-launch prelude) ============================
__global__ void count_kernel(const int* __restrict__ ei, int* __restrict__ deg) {
    int e = blockIdx.x * blockDim.x + threadIdx.x;
    if (e < NEDGES) atomicAdd(&deg[ei[NEDGES + e]], 1);
}

// Single-pass scan: each block reduces all preceding degrees itself, then
// scans its own 1024-node chunk. Emits rowptr + cur.
__global__ __launch_bounds__(256) void scanall_kernel(
        const int* __restrict__ deg,
        int* __restrict__ rowptr, int* __restrict__ cur) {
    __shared__ int ws[8];
    __shared__ int pre;
    const int tid = threadIdx.x, lane = tid & 31, wid = tid >> 5;
    const int b = blockIdx.x;

    int off = 0;
    for (int i4 = tid; i4 < b * 256; i4 += 256) {
        int4 v = ((const int4*)deg)[i4];
        off += (v.x + v.y) + (v.z + v.w);
    }
    #pragma unroll
    for (int o = 16; o > 0; o >>= 1) off += __shfl_down_sync(~0u, off, o);
    if (lane == 0) ws[wid] = off;
    __syncthreads();
    if (wid == 0) {
        int t = (lane < 8) ? ws[lane] : 0;
        #pragma unroll
        for (int o = 4; o > 0; o >>= 1) t += __shfl_down_sync(~0u, t, o);
        if (lane == 0) pre = t;
    }
    __syncthreads();

    int i4 = b * 256 + tid;
    int4 v = make_int4(0, 0, 0, 0);
    if (i4 < NNODES / 4) v = ((const int4*)deg)[i4];
    int local = (v.x + v.y) + (v.z + v.w);
    int s = local;
    #pragma unroll
    for (int o = 1; o < 32; o <<= 1) {
        int t = __shfl_up_sync(~0u, s, o);
        if (lane >= o) s += t;
    }
    if (lane == 31) ws[wid] = s;
    __syncthreads();
    if (wid == 0) {
        int t = (lane < 8) ? ws[lane] : 0;
        #pragma unroll
        for (int o = 1; o < 8; o <<= 1) {
            int u = __shfl_up_sync(~0u, t, o);
            if (lane >= o) t += u;
        }
        if (lane < 8) ws[lane] = t;
    }
    __syncthreads();
    int excl = pre + (wid ? ws[wid - 1] : 0) + (s - local);
    if (i4 < NNODES / 4) {
        int idx = i4 * 4;
        int p0 = excl + v.x, p1 = p0 + v.y, p2 = p1 + v.z, p3 = p2 + v.w;
        cur[idx] = excl; cur[idx + 1] = p0; cur[idx + 2] = p1; cur[idx + 3] = p2;
        rowptr[idx + 1] = p0; rowptr[idx + 2] = p1;
        rowptr[idx + 3] = p2; rowptr[idx + 4] = p3;
    }
    if (b == 0 && tid == 0) rowptr[0] = 0;
}

__global__ void fill_kernel(const int* __restrict__ ei,
                            int* __restrict__ cur, int* __restrict__ col) {
    int e = blockIdx.x * blockDim.x + threadIdx.x;
    if (e >= NEDGES) return;
    int slot = atomicAdd(&cur[ei[NEDGES + e]], 1);
    col[slot] = ei[e];
}

// ==== W pre-split (W1/W2/Wc) + deg zeroing ================================
#define WSP_N1 (NLAYERS * 2 * HID * HID)
__global__ void wsplit_kernel(const float* __restrict__ W1,
                              const float* __restrict__ W2,
                              const float* __restrict__ Wc) {
    int i = blockIdx.x * blockDim.x + threadIdx.x;
    if (i < NNODES) g_deg[i] = 0;
    if (i < WSP_N1) {
        int e = i & (HID * HID - 1);
        int m = (i >> 14) & 1;           // 0 = W1, 1 = W2
        int l = i >> 15;                 // layer
        int k = e >> 7, n = e & 127;
        const float* W = (m ? W2 : W1) + (size_t)l * HID * HID;
        float v = W[k * HID + n];
        __nv_bfloat16 hi = __float2bfloat16(v);
        __nv_bfloat16 lo = __float2bfloat16(v - __bfloat162float(hi));
        __nv_bfloat16* base = g_wsp + ((size_t)l * 4 + m * 2) * HID * HID;
        base[n * HID + k] = hi;
        base[HID * HID + n * HID + k] = lo;
    } else {
        int j = i - WSP_N1;
        if (j >= OUTC * HID) return;
        int n = j / HID, k = j - n * HID;
        float v = Wc[k * OUTC + n];
        __nv_bfloat16 hi = __float2bfloat16(v);
        __nv_bfloat16 lo = __float2bfloat16(v - __bfloat162float(hi));
        g_wc[n * HID + k] = hi;
        g_wc[64 * HID + n * HID + k] = lo;
    }
}

// ===== gather: z[d,:] = h[d,:] + sum_{s in N(d)} h[s,:] -> split bf16 ======
__global__ __launch_bounds__(256) void gather_kernel(
        const float* __restrict__ h,
        const int* __restrict__ rowptr, const int* __restrict__ col) {
    int node = (blockIdx.x * blockDim.x + threadIdx.x) >> 5;
    if (node >= NNODES) return;
    int lane = threadIdx.x & 31;
    int beg = rowptr[node], end = rowptr[node + 1];
    float4 acc = *(const float4*)(h + (size_t)node * HID + lane * 4);
    int j = beg;
    while (j < end) {
        int n = min(32, end - j);
        int myc = (lane < n) ? col[j + lane] : 0;
        int t = 0;
        for (; t + 7 < n; t += 8) {
            float4 vv[8];
            #pragma unroll
            for (int u = 0; u < 8; u++) {
                int s = __shfl_sync(~0u, myc, t + u);
                vv[u] = *(const float4*)(h + (size_t)s * HID + lane * 4);
            }
            #pragma unroll
            for (int u = 0; u < 8; u++) {
                acc.x += vv[u].x; acc.y += vv[u].y;
                acc.z += vv[u].z; acc.w += vv[u].w;
            }
        }
        for (; t + 3 < n; t += 4) {
            float4 vv[4];
            #pragma unroll
            for (int u = 0; u < 4; u++) {
                int s = __shfl_sync(~0u, myc, t + u);
                vv[u] = *(const float4*)(h + (size_t)s * HID + lane * 4);
            }
            #pragma unroll
            for (int u = 0; u < 4; u++) {
                acc.x += vv[u].x; acc.y += vv[u].y;
                acc.z += vv[u].z; acc.w += vv[u].w;
            }
        }
        for (; t < n; t++) {
            int s = __shfl_sync(~0u, myc, t);
            float4 v = *(const float4*)(h + (size_t)s * HID + lane * 4);
            acc.x += v.x; acc.y += v.y; acc.z += v.z; acc.w += v.w;
        }
        j += n;
    }
    float f[4] = {acc.x, acc.y, acc.z, acc.w};
    uint32_t hw[2], lw[2];
    #pragma unroll
    for (int p = 0; p < 2; p++) {
        float v0 = f[2 * p], v1 = f[2 * p + 1];
        __nv_bfloat16 h0 = __float2bfloat16(v0), h1 = __float2bfloat16(v1);
        hw[p] = (uint32_t)__bfloat16_as_ushort(h0) |
                ((uint32_t)__bfloat16_as_ushort(h1) << 16);
        lw[p] = pack_bf16x2(v0 - __bfloat162float(h0), v1 - __bfloat162float(h1));
    }
    size_t off = (size_t)node * HID + lane * 4;   // bf16 elements
    *(uint2*)((char*)g_zhi + off * 2) = make_uint2(hw[0], hw[1]);
    *(uint2*)((char*)g_zlo + off * 2) = make_uint2(lw[0], lw[1]);
}

// ===================== tensor-core fused GIN MLP (mma.sync) ================
// 256 threads / 8 warps. Warp tile 32m x 64n (mg 0..3, ng 0..1): balanced
// A/B ldsm (6/kc) and B fragments hoisted across the 3 split terms
// (12 ldsm/kc/warp vs 27 in the 16x128 form) -> 2.25x less smem traffic.
// SMEM rows padded to 272B (17 x 16B) -> ldmatrix conflict-free.
// Layout: Ahi, Alo, B1hi, B1lo, B2hi, B2lo (6 x 34816B) + biases.
#define SROW 272
#define ATB  (128 * SROW)
#define MLP_SMEM (6 * ATB + 1536)

__device__ __forceinline__ void stage_mat(char* dst, const uint4* src,
                                          int tid, int nrow) {
    for (int i = tid; i < nrow * 16; i += 256) {
        int row = i >> 4, ch = i & 15;
        *(uint4*)(dst + row * SROW + ch * 16) = src[i];
    }
}

// One GEMM phase over the warp's 32m x (16*NJP)n tile.
// acc flat: index (mi*NJP + jp)*2 + half  ==  mi*2*NJP + j  (j = n8 tile).
template <int NJP>
__device__ __forceinline__ void phaseW(float (*acc)[4],
        uint32_t aAh, uint32_t aAl, uint32_t aBh, uint32_t aBl) {
    #pragma unroll 1
    for (int kc = 0; kc < 8; kc++) {
        uint32_t a0h[4], a1h[4], a0l[4], a1l[4];
        ldsm_x4(a0h, aAh + kc * 32);
        ldsm_x4(a1h, aAh + 16 * SROW + kc * 32);
        ldsm_x4(a0l, aAl + kc * 32);
        ldsm_x4(a1l, aAl + 16 * SROW + kc * 32);
        #pragma unroll
        for (int jp = 0; jp < NJP; jp++) {
            uint32_t bh[4], bl[4];
            ldsm_x4(bh, aBh + jp * 16 * SROW + kc * 32);
            ldsm_x4(bl, aBl + jp * 16 * SROW + kc * 32);
            float* c00 = acc[(0 * NJP + jp) * 2];
            float* c01 = acc[(0 * NJP + jp) * 2 + 1];
            float* c10 = acc[(1 * NJP + jp) * 2];
            float* c11 = acc[(1 * NJP + jp) * 2 + 1];
            mma16816(c00, a0h, bh); mma16816(c01, a0h, bh + 2);
            mma16816(c10, a1h, bh); mma16816(c11, a1h, bh + 2);
            mma16816(c00, a0l, bh); mma16816(c01, a0l, bh + 2);
            mma16816(c10, a1l, bh); mma16816(c11, a1l, bh + 2);
            mma16816(c00, a0h, bl); mma16816(c01, a0h, bl + 2);
            mma16816(c10, a1h, bl); mma16816(c11, a1h, bl + 2);
        }
    }
}

// relu + hi/lo split of acc (32m x 64n warp tile) back into the A tiles.
__device__ __forceinline__ void epi_to_smem(float (*acc)[4], char* ah, char* al,
                                            int mg, int ng, int lane) {
    int rl = lane >> 2;
    #pragma unroll
    for (int mi = 0; mi < 2; mi++) {
        int rowL = mg * 32 + mi * 16 + rl, rowH = rowL + 8;
        #pragma unroll
        for (int j = 0; j < 8; j++) {
            float* a = acc[mi * 8 + j];
            int boff = ng * 128 + 16 * j + (lane & 3) * 4;
            float v0 = fmaxf(a[0], 0.f), v1 = fmaxf(a[1], 0.f);
            float v2 = fmaxf(a[2], 0.f), v3 = fmaxf(a[3], 0.f);
            __nv_bfloat16 h0 = __float2bfloat16(v0), h1 = __float2bfloat16(v1);
            __nv_bfloat16 h2 = __float2bfloat16(v2), h3 = __float2bfloat16(v3);
            *(uint32_t*)(ah + rowL * SROW + boff) =
                (uint32_t)__bfloat16_as_ushort(h0) |
                ((uint32_t)__bfloat16_as_ushort(h1) << 16);
            *(uint32_t*)(ah + rowH * SROW + boff) =
                (uint32_t)__bfloat16_as_ushort(h2) |
                ((uint32_t)__bfloat16_as_ushort(h3) << 16);
            *(uint32_t*)(al + rowL * SROW + boff) =
                pack_bf16x2(v0 - __bfloat162float(h0), v1 - __bfloat162float(h1));
            *(uint32_t*)(al + rowH * SROW + boff) =
                pack_bf16x2(v2 - __bfloat162float(h2), v3 - __bfloat162float(h3));
        }
    }
}

__global__ __launch_bounds__(256) void mlp_mma_kernel(
        float* __restrict__ hout, int layer, int last,
        const float* __restrict__ b1, const float* __restrict__ b2,
        const float* __restrict__ bc, float* __restrict__ out) {
    extern __shared__ char sm[];
    char* ah = sm;
    char* al = sm + ATB;
    char* b1h = sm + 2 * ATB;          // also Wc slot for last layer
    char* b2h = sm + 4 * ATB;
    float* bs1 = (float*)(sm + 6 * ATB);
    float* bs2 = bs1 + HID;
    float* bs3 = bs2 + HID;            // 64 floats (bc padded)

    const int tid = threadIdx.x;
    const int warp = tid >> 5, lane = tid & 31;
    const int mg = warp >> 1;          // 0..3: 32-row group
    const int ng = warp & 1;           // 0..1: 64-col group
    const int tile = blockIdx.x;
    const int row0 = tile * 128;
    const int rmax = NNODES - row0;

    // ---- stage A (split z) + W1^T + W2^T (split) + biases ----
    stage_mat(ah,  (const uint4*)((const char*)g_zhi + (size_t)tile * 32768), tid, 128);
    stage_mat(al,  (const uint4*)((const char*)g_zlo + (size_t)tile * 32768), tid, 128);
    stage_mat(b1h, (const uint4*)(g_wsp + ((size_t)layer * 4 + 0) * HID * HID), tid, 128);
    stage_mat(b1h + ATB, (const uint4*)(g_wsp + ((size_t)layer * 4 + 1) * HID * HID), tid, 128);
    stage_mat(b2h, (const uint4*)(g_wsp + ((size_t)layer * 4 + 2) * HID * HID), tid, 128);
    stage_mat(b2h + ATB, (const uint4*)(g_wsp + ((size_t)layer * 4 + 3) * HID * HID), tid, 128);
    if (tid < HID) { bs1[tid] = b1[tid]; bs2[tid] = b2[tid]; }
    if (tid < 64)  bs3[tid] = (tid < OUTC) ? bc[tid] : 0.f;
    __syncthreads();

    // ldmatrix lane addressing
    const int rr = lane & 7, g = lane >> 3;
    const uint32_t aRow = (mg * 32 + (g & 1) * 8 + rr) * SROW + (g >> 1) * 16;
    const uint32_t aAh = smem_u32(ah) + aRow;
    const uint32_t aAl = smem_u32(al) + aRow;
    const uint32_t bL = ((g >> 1) * 8 + rr) * SROW + (g & 1) * 16;
    const uint32_t aB1h = smem_u32(b1h) + bL + ng * 64 * SROW;
    const uint32_t aB1l = smem_u32(b1h + ATB) + bL + ng * 64 * SROW;
    const uint32_t aB2h = smem_u32(b2h) + bL + ng * 64 * SROW;
    const uint32_t aB2l = smem_u32(b2h + ATB) + bL + ng * 64 * SROW;

    const int cl = (lane & 3) * 2;
    const int rl = lane >> 2;

    float acc[16][4];   // (mi*8 + j), j = n8 tile within warp's 64 cols

    // ---- phase 1: hidden = relu(z @ W1 + b1) ----
    #pragma unroll
    for (int mi = 0; mi < 2; mi++)
        #pragma unroll
        for (int j = 0; j < 8; j++) {
            int c = ng * 64 + 8 * j + cl;
            float v0 = bs1[c], v1 = bs1[c + 1];
            float* a = acc[mi * 8 + j];
            a[0] = v0; a[1] = v1; a[2] = v0; a[3] = v1;
        }
    phaseW<4>(acc, aAh, aAl, aB1h, aB1l);
    epi_to_smem(acc, ah, al, mg, ng, lane);
    __syncthreads();                    // col-halves of rows from 2 warps

    if (last) {                         // overwrite B1 slots with Wc (split)
        stage_mat(b1h, (const uint4*)g_wc, tid, 64);
        stage_mat(b1h + ATB, (const uint4*)(g_wc + 64 * HID), tid, 64);
        __syncthreads();
    }

    // ---- phase 2: hfin = relu(hidden @ W2 + b2) ----
    #pragma unroll
    for (int mi = 0; mi < 2; mi++)
        #pragma unroll
        for (int j = 0; j < 8; j++) {
            int c = ng * 64 + 8 * j + cl;
            float v0 = bs2[c], v1 = bs2[c + 1];
            float* a = acc[mi * 8 + j];
            a[0] = v0; a[1] = v1; a[2] = v0; a[3] = v1;
        }
    phaseW<4>(acc, aAh, aAl, aB2h, aB2l);

    if (!last) {
        // epilogue: relu -> hout fp32 (warp tile 32m x 64n)
        #pragma unroll
        for (int mi = 0; mi < 2; mi++) {
            int rowL = mg * 32 + mi * 16 + rl, rowH = rowL + 8;
            bool okL = rowL < rmax, okH = rowH < rmax;
            #pragma unroll
            for (int j = 0; j < 8; j++) {
                float* a = acc[mi * 8 + j];
                int c = ng * 64 + 8 * j + cl;
                if (okL) {
                    float2 o = make_float2(fmaxf(a[0], 0.f), fmaxf(a[1], 0.f));
                    *(float2*)(hout + (size_t)(row0 + rowL) * HID + c) = o;
                }
                if (okH) {
                    float2 o = make_float2(fmaxf(a[2], 0.f), fmaxf(a[3], 0.f));
                    *(float2*)(hout + (size_t)(row0 + rowH) * HID + c) = o;
                }
            }
        }
        return;
    }

    // ---- last layer: keep hfin in SMEM, fused classifier phase ----
    epi_to_smem(acc, ah, al, mg, ng, lane);
    __syncthreads();

    float acc3[8][4];   // (mi*4 + j), warp covers n in [ng*32, ng*32+32)
    #pragma unroll
    for (int mi = 0; mi < 2; mi++)
        #pragma unroll
        for (int j = 0; j < 4; j++) {
            int c = ng * 32 + 8 * j + cl;
            float v0 = bs3[c], v1 = bs3[c + 1];
            float* a = acc3[mi * 4 + j];
            a[0] = v0; a[1] = v1; a[2] = v0; a[3] = v1;
        }
    phaseW<2>(acc3, aAh, aAl,
              smem_u32(b1h) + bL + ng * 32 * SROW,
              smem_u32(b1h + ATB) + bL + ng * 32 * SROW);

    {
        int jmax = ng ? 1 : 4;          // OUTC=40: ng0 -> cols 0..31, ng1 -> 32..39
        #pragma unroll
        for (int mi = 0; mi < 2; mi++) {
            int rowL = mg * 32 + mi * 16 + rl, rowH = rowL + 8;
            bool okL = rowL < rmax, okH = rowH < rmax;
            for (int j = 0; j < jmax; j++) {
                float* a = acc3[mi * 4 + j];
                int c = ng * 32 + 8 * j + cl;
                if (okL) {
                    float2 o = make_float2(a[0], a[1]);
                    *(float2*)(out + (size_t)(row0 + rowL) * OUTC + c) = o;
                }
                if (okH) {
                    float2 o = make_float2(a[2], a[3]);
                    *(float2*)(out + (size_t)(row0 + rowH) * OUTC + c) = o;
                }
            }
        }
    }
}

// ---------------- launch ----------------
extern "C" void kernel_launch(void* const* d_in, const int* in_sizes, int n_in,
                              void* d_out, int out_size) {
    (void)in_sizes; (void)n_in; (void)out_size;
    const float* x  = (const float*)d_in[0];
    const int*   ei = (const int*)d_in[2];       // int32 (JAX demotes int64)
    const float* W1 = (const float*)d_in[3];
    const float* b1 = (const float*)d_in[4];
    const float* W2 = (const float*)d_in[5];
    const float* b2 = (const float*)d_in[6];
    const float* Wc = (const float*)d_in[7];
    const float* bc = (const float*)d_in[8];
    float* out = (float*)d_out;

    float* hbuf;
    int *deg, *rowptr, *cur, *col;
    cudaGetSymbolAddress((void**)&hbuf, g_h);
    cudaGetSymbolAddress((void**)&deg, g_deg);
    cudaGetSymbolAddress((void**)&rowptr, g_rowptr);
    cudaGetSymbolAddress((void**)&cur, g_cur);
    cudaGetSymbolAddress((void**)&col, g_col);

    cudaFuncSetAttribute(mlp_mma_kernel,
                         cudaFuncAttributeMaxDynamicSharedMemorySize, MLP_SMEM);

    const int EB = (NEDGES + 255) / 256;
    const int GB = (NNODES * 32 + 255) / 256;
    const int WB = (WSP_N1 + OUTC * HID + 255) / 256;

    // 4-launch prelude: wsplit(+deg zero), count, scanall, fill
    wsplit_kernel<<<WB, 256>>>(W1, W2, Wc);
    count_kernel<<<EB, 256>>>(ei, deg);
    scanall_kernel<<<SCB, 256>>>(deg, rowptr, cur);
    fill_kernel<<<EB, 256>>>(ei, cur, col);

    // layer 0 (h = x)
    gather_kernel<<<GB, 256>>>(x, rowptr, col);
    mlp_mma_kernel<<<NTILES, 256, MLP_SMEM>>>(hbuf, 0, 0, b1, b2, bc, out);

    for (int l = 1; l < NLAYERS; l++) {
        gather_kernel<<<GB, 256>>>(hbuf, rowptr, col);
        mlp_mma_kernel<<<NTILES, 256, MLP_SMEM>>>(
            hbuf, l, (l == NLAYERS - 1) ? 1 : 0,
            b1 + (size_t)l * HID, b2 + (size_t)l * HID, bc, out);
    }
}